// round 10
// baseline (speedup 1.0000x reference)
#include <cuda_runtime.h>
#include <cuda_bf16.h>
#include <math.h>
#include <cstdint>

#define BB 8
#define TT 2048
#define CC 1024
#define HH 64

// bf16 hi/lo tensors
__device__ __nv_bfloat16 g_xh[BB*TT*CC], g_xl[BB*TT*CC];   // x  [m][c]
__device__ __nv_bfloat16 g_qh[BB*TT*HH], g_ql[BB*TT*HH];   // q  [b][t][h] (pre-scaled x log2e)
__device__ __nv_bfloat16 g_kh[BB*TT*HH], g_kl[BB*TT*HH];   // k  [b][t][h]
__device__ __nv_bfloat16 g_vth[BB*HH*TT], g_vtl[BB*HH*TT]; // v^T [b][h][t]
__device__ __nv_bfloat16 g_wt_hi[192*CC];                  // W^T [n][k], n = mat*64+h
__device__ __nv_bfloat16 g_wt_lo[192*CC];
__device__ int g_ctr  = 0;
__device__ int g_done = 0;

// ---- mma.sync m16n8k16 bf16 (sm_80 baseline) ----
__device__ __forceinline__ void mma16816(float* c, const uint32_t* a, const uint32_t* b) {
    asm volatile(
        "mma.sync.aligned.m16n8k16.row.col.f32.bf16.bf16.f32 "
        "{%0,%1,%2,%3}, {%4,%5,%6,%7}, {%8,%9}, {%0,%1,%2,%3};"
        : "+f"(c[0]), "+f"(c[1]), "+f"(c[2]), "+f"(c[3])
        : "r"(a[0]), "r"(a[1]), "r"(a[2]), "r"(a[3]), "r"(b[0]), "r"(b[1]));
}
// ---- ldmatrix x4 (sm_75 baseline) ----
__device__ __forceinline__ void ldsm4(uint32_t* r, uint32_t addr) {
    asm volatile("ldmatrix.sync.aligned.m8n8.x4.shared.b16 {%0,%1,%2,%3}, [%4];"
        : "=r"(r[0]), "=r"(r[1]), "=r"(r[2]), "=r"(r[3]) : "r"(addr) : "memory");
}
// ---- cp.async (sm_80 baseline) ----
#define CP16(dst, src) asm volatile("cp.async.cg.shared.global [%0], [%1], 16;" :: "r"(dst), "l"(src) : "memory")
#define CP_COMMIT()    asm volatile("cp.async.commit_group;" ::: "memory")
#define CP_WAIT1()     asm volatile("cp.async.wait_group 1;" ::: "memory")

__device__ __forceinline__ uint32_t smem_u32(const void* p) {
    uint32_t a;
    asm("{ .reg .u64 t; cvta.to.shared.u64 t, %1; cvt.u32.u64 %0, t; }" : "=r"(a) : "l"(p));
    return a;
}
__device__ __forceinline__ float ex2(float x) {
    float y; asm("ex2.approx.f32 %0, %1;" : "=f"(y) : "f"(x)); return y;
}
__device__ __forceinline__ uint32_t hi2(float a, float b) {
    return ((uint32_t)__bfloat16_as_ushort(__float2bfloat16(b)) << 16) |
           (uint32_t)__bfloat16_as_ushort(__float2bfloat16(a));
}
__device__ __forceinline__ uint32_t lo2(float a, float b) {
    float ra = a - __bfloat162float(__float2bfloat16(a));
    float rb = b - __bfloat162float(__float2bfloat16(b));
    return hi2(ra, rb);
}

// ---------------------------------------------------------------------------
// Prep kernels: W^T hi/lo and x hi/lo.
// ---------------------------------------------------------------------------
__global__ __launch_bounds__(256) void wprep_kernel(
    const float* __restrict__ Wq, const float* __restrict__ Wk,
    const float* __restrict__ Wv)
{
    int n = blockIdx.x;                 // 0..191
    const float* W = (n < 64) ? Wq : (n < 128) ? Wk : Wv;
    int h = n & 63;
    for (int k = threadIdx.x; k < CC; k += 256) {
        float v = W[(size_t)k * HH + h];
        __nv_bfloat16 hi = __float2bfloat16(v);
        g_wt_hi[(size_t)n * CC + k] = hi;
        g_wt_lo[(size_t)n * CC + k] = __float2bfloat16(v - __bfloat162float(hi));
    }
}

__global__ __launch_bounds__(256) void xprep_kernel(const float* __restrict__ x)
{
    const int stride = gridDim.x * blockDim.x;
    for (int i = blockIdx.x * blockDim.x + threadIdx.x; i < BB*TT*CC/4; i += stride) {
        float4 v = *(const float4*)&x[(size_t)i * 4];
        uint2 hv, lv;
        hv.x = hi2(v.x, v.y);  hv.y = hi2(v.z, v.w);
        lv.x = lo2(v.x, v.y);  lv.y = lo2(v.z, v.w);
        *(uint2*)&g_xh[(size_t)i * 4] = hv;
        *(uint2*)&g_xl[(size_t)i * 4] = lv;
    }
}

// ---------------------------------------------------------------------------
// Projection GEMM: cp.async double-buffered, ldmatrix fragments.
// Grid (128, 2): blockIdx.x = 128-row M tile, blockIdx.y = 96-col N half.
// 256 thr (8 warps: 4M x 2N; warp tile 32m x 48n).  K chunks of 32.
// smem per stage (bf16): Ah@0(5120) Al@5120 Bh@10240(3840) Bl@14080
// stage stride 17920;  2 stages = 35840 bf16 = 71680 B
// ---------------------------------------------------------------------------
#define PROJ_SMEM 71680
#define PSS 17920

__global__ __launch_bounds__(256, 1) void proj_mma_kernel()
{
    extern __shared__ __nv_bfloat16 sb[];
    const uint32_t sbase = smem_u32(sb);

    const int tid  = threadIdx.x;
    const int wid  = tid >> 5;
    const int lane = tid & 31;
    const int g    = lane >> 2;
    const int tg   = lane & 3;
    const int m0   = blockIdx.x * 128;
    const int ny   = blockIdx.y;            // 0 or 1: N rows [ny*96, ny*96+96)
    const int m0w  = (wid >> 1) * 32;
    const int n0w  = (wid & 1) * 48;

    // ldmatrix per-lane offsets
    const int m_off = (lane & 7) + ((lane >> 3) & 1) * 8;
    const int kA    = (lane >> 4) * 8;
    const int n_off = (lane & 7) + ((lane >> 4) & 1) * 8;
    const int kB    = ((lane >> 3) & 1) * 8;

    auto issue_chunk = [&](int kc, int s) {
        const int k0 = kc * 32;
        const uint32_t st = sbase + 2 * (s * PSS);
        #pragma unroll
        for (int t = 0; t < 4; t++) {            // A: 1024 x 16B
            int e = tid + t * 256;
            int arr = e >> 9;
            int ee  = e & 511;
            int row = ee >> 2, q = ee & 3;
            const __nv_bfloat16* src =
                (arr ? g_xl : g_xh) + (size_t)(m0 + row) * CC + k0 + q * 8;
            CP16(st + 2 * (arr * 5120 + row * 40 + q * 8), src);
        }
        #pragma unroll
        for (int t = 4; t < 7; t++) {            // B: 768 x 16B (96 rows x 2 arrays)
            int e2 = tid + t * 256 - 1024;       // 0..767
            int arr = (e2 >= 384);
            int ee  = arr ? e2 - 384 : e2;
            int row = ee >> 2, q = ee & 3;
            const __nv_bfloat16* src =
                (arr ? g_wt_lo : g_wt_hi) + (size_t)(ny * 96 + row) * CC + k0 + q * 8;
            CP16(st + 2 * (10240 + arr * 3840 + row * 40 + q * 8), src);
        }
    };

    float acc[2][6][4];
    #pragma unroll
    for (int mt = 0; mt < 2; mt++)
        #pragma unroll
        for (int nt = 0; nt < 6; nt++)
            #pragma unroll
            for (int i = 0; i < 4; i++) acc[mt][nt][i] = 0.f;

    issue_chunk(0, 0); CP_COMMIT();
    issue_chunk(1, 1); CP_COMMIT();

    for (int kc = 0; kc < 32; kc++) {
        const int s = kc & 1;
        CP_WAIT1();
        __syncthreads();

        const uint32_t ah_b = sbase + 2 * (s * PSS);
        const uint32_t al_b = ah_b + 2 * 5120;
        const uint32_t bh_b = ah_b + 2 * 10240;
        const uint32_t bl_b = ah_b + 2 * 14080;

        #pragma unroll
        for (int ks = 0; ks < 32; ks += 16) {
            uint32_t ah[2][4], al[2][4];
            #pragma unroll
            for (int mt = 0; mt < 2; mt++) {
                int ro = (m0w + mt * 16 + m_off) * 40 + ks + kA;
                ldsm4(ah[mt], ah_b + 2 * ro);
                ldsm4(al[mt], al_b + 2 * ro);
            }
            #pragma unroll
            for (int p = 0; p < 3; p++) {
                int ro = (n0w + p * 16 + n_off) * 40 + ks + kB;
                uint32_t bh[4], bl[4];
                ldsm4(bh, bh_b + 2 * ro);
                ldsm4(bl, bl_b + 2 * ro);
                #pragma unroll
                for (int hf = 0; hf < 2; hf++) {
                    int nt = p * 2 + hf;
                    #pragma unroll
                    for (int mt = 0; mt < 2; mt++) {
                        mma16816(acc[mt][nt], ah[mt], bh + hf * 2);
                        mma16816(acc[mt][nt], ah[mt], bl + hf * 2);
                        mma16816(acc[mt][nt], al[mt], bh + hf * 2);
                    }
                }
            }
        }
        __syncthreads();
        if (kc + 2 < 32) issue_chunk(kc + 2, s);
        CP_COMMIT();
    }

    // ---- epilogue: Q (x 0.125*log2e) / K -> [t][h] hi/lo;  V -> transpose ----
    const int b  = m0 >> 11;
    const int t0 = m0 & 2047;
    const float QSC = 0.125f * 1.44269504088896f;   // fold log2e for exp2 softmax
    __nv_bfloat16* sTh = sb;               // [64][136]
    __nv_bfloat16* sTl = sb + 64 * 136;

    #pragma unroll
    for (int nt = 0; nt < 6; nt++) {
        int nbase = ny * 96 + n0w + nt * 8;
        #pragma unroll
        for (int mt = 0; mt < 2; mt++) {
            int row = m0w + mt * 16 + g;
            float c0 = acc[mt][nt][0], c1 = acc[mt][nt][1];
            float c2 = acc[mt][nt][2], c3 = acc[mt][nt][3];
            if (nbase < 64) {
                c0 *= QSC; c1 *= QSC; c2 *= QSC; c3 *= QSC;
                size_t base0 = (size_t)(m0 + row) * HH + nbase + 2 * tg;
                size_t base1 = base0 + 8 * HH;
                *(uint32_t*)&g_qh[base0] = hi2(c0, c1);
                *(uint32_t*)&g_ql[base0] = lo2(c0, c1);
                *(uint32_t*)&g_qh[base1] = hi2(c2, c3);
                *(uint32_t*)&g_ql[base1] = lo2(c2, c3);
            } else if (nbase < 128) {
                size_t base0 = (size_t)(m0 + row) * HH + (nbase - 64) + 2 * tg;
                size_t base1 = base0 + 8 * HH;
                *(uint32_t*)&g_kh[base0] = hi2(c0, c1);
                *(uint32_t*)&g_kl[base0] = lo2(c0, c1);
                *(uint32_t*)&g_kh[base1] = hi2(c2, c3);
                *(uint32_t*)&g_kl[base1] = lo2(c2, c3);
            } else {
                int h = nbase - 128 + 2 * tg;
                __nv_bfloat16 h0 = __float2bfloat16(c0), h1 = __float2bfloat16(c1);
                __nv_bfloat16 h2 = __float2bfloat16(c2), h3 = __float2bfloat16(c3);
                sTh[h * 136 + row]           = h0;
                sTh[(h + 1) * 136 + row]     = h1;
                sTh[h * 136 + row + 8]       = h2;
                sTh[(h + 1) * 136 + row + 8] = h3;
                sTl[h * 136 + row]           = __float2bfloat16(c0 - __bfloat162float(h0));
                sTl[(h + 1) * 136 + row]     = __float2bfloat16(c1 - __bfloat162float(h1));
                sTl[h * 136 + row + 8]       = __float2bfloat16(c2 - __bfloat162float(h2));
                sTl[(h + 1) * 136 + row + 8] = __float2bfloat16(c3 - __bfloat162float(h3));
            }
        }
    }
    __syncthreads();
    if (ny == 1) {   // only the N-half that owns V does the transpose copy
        #pragma unroll
        for (int t = 0; t < 8; t++) {
            int e   = tid + t * 256;
            int arr = e >> 10;
            int ee  = e & 1023;
            int h   = ee >> 4;
            int q   = ee & 15;
            uint4 v4 = *(const uint4*)&(arr ? sTl : sTh)[h * 136 + q * 8];
            __nv_bfloat16* dst = arr ? g_vtl : g_vth;
            *(uint4*)&dst[(size_t)(b * 64 + h) * 2048 + t0 + q * 8] = v4;
        }
    }
}

// ---------------------------------------------------------------------------
// Attention: cp.async double-buffered K/V, ldmatrix frags, Q frags hoisted,
// exp2-domain softmax interleaved with the PV GEMM.  BM=BN=64, 128 threads,
// 304 persistent CTAs, 256 jobs heavy-first.
// smem (bf16, stride 72): Qh@0(4608) Ql@4608; stage s @9216+s*18432:
//   Kh+0 Kl+4608 Vh+9216 Vl+13824.   total 46080 bf16 = 92160 B
// ---------------------------------------------------------------------------
#define ATTN_CTAS 304
#define ATTN_SMEM 92160

__global__ __launch_bounds__(128, 1) void attn_mma_kernel(float* __restrict__ out)
{
    extern __shared__ __nv_bfloat16 sab[];
    const uint32_t sbase = smem_u32(sab);
    __shared__ int sJob;

    const int tid  = threadIdx.x;
    const int wid  = tid >> 5;
    const int lane = tid & 31;
    const int g    = lane >> 2;
    const int tg   = lane & 3;
    const int rw   = wid * 16;

    const int m_off = (lane & 7) + ((lane >> 3) & 1) * 8;
    const int kA    = (lane >> 4) * 8;
    const int n_off = (lane & 7) + ((lane >> 4) & 1) * 8;
    const int kB    = ((lane >> 3) & 1) * 8;

    for (;;) {
        if (tid == 0) sJob = atomicAdd(&g_ctr, 1);
        __syncthreads();
        const int job = sJob;
        if (job >= 256) break;

        const int qt = 31 - (job >> 3);
        const int b  = job & 7;
        const int q0 = qt * 64;

        auto issue_kv = [&](int t, int s) {
            const int kv0 = t * 64;
            const uint32_t st = sbase + 2 * (9216 + s * 18432);
            #pragma unroll
            for (int tt = 0; tt < 16; tt++) {
                int e = tid + tt * 128;
                int arr = e >> 9;            // 0:Kh 1:Kl 2:Vh 3:Vl
                int ee  = e & 511;
                int row = ee >> 3, q = ee & 7;
                const __nv_bfloat16* src;
                if (arr == 0)      src = g_kh  + ((size_t)b * TT + kv0 + row) * HH + q * 8;
                else if (arr == 1) src = g_kl  + ((size_t)b * TT + kv0 + row) * HH + q * 8;
                else if (arr == 2) src = g_vth + ((size_t)(b * 64 + row)) * 2048 + kv0 + q * 8;
                else               src = g_vtl + ((size_t)(b * 64 + row)) * 2048 + kv0 + q * 8;
                CP16(st + 2 * (arr * 4608 + row * 72 + q * 8), src);
            }
        };

        // group 0: Q + KV chunk 0;  group 1: KV chunk 1
        #pragma unroll
        for (int tt = 0; tt < 8; tt++) {
            int e = tid + tt * 128;
            int arr = e >> 9;
            int ee  = e & 511;
            int row = ee >> 3, q = ee & 7;
            const __nv_bfloat16* src =
                (arr ? g_ql : g_qh) + ((size_t)b * TT + q0 + row) * HH + q * 8;
            CP16(sbase + 2 * (arr * 4608 + row * 72 + q * 8), src);
        }
        issue_kv(0, 0); CP_COMMIT();
        if (qt >= 1) issue_kv(1, 1);
        CP_COMMIT();

        // ---- hoist Q fragments into registers (Q arrives with group 0) ----
        CP_WAIT1();
        __syncthreads();
        uint32_t qfh[4][4], qfl[4][4];
        #pragma unroll
        for (int i = 0; i < 4; i++) {
            int ro = (rw + m_off) * 72 + i * 16 + kA;
            ldsm4(qfh[i], sbase + 2 * ro);
            ldsm4(qfl[i], sbase + 2 * (4608 + ro));
        }

        float m_i[2] = {-INFINITY, -INFINITY};
        float l_i[2] = {0.f, 0.f};
        float o[8][4];
        #pragma unroll
        for (int nt = 0; nt < 8; nt++)
            #pragma unroll
            for (int i = 0; i < 4; i++) o[nt][i] = 0.f;

        for (int t = 0; t <= qt; t++) {
            const int s = t & 1;
            CP_WAIT1();
            __syncthreads();

            const uint32_t kh_b = sbase + 2 * (9216 + s * 18432);
            const uint32_t kl_b = kh_b + 2 * 4608;
            const uint32_t vh_b = kh_b + 2 * 9216;
            const uint32_t vl_b = kh_b + 2 * 13824;

            // ---- S = Q K^T (S already in log2-e domain via Q prescale) ----
            float sc[8][4];
            #pragma unroll
            for (int nt = 0; nt < 8; nt++)
                #pragma unroll
                for (int i = 0; i < 4; i++) sc[nt][i] = 0.f;

            #pragma unroll
            for (int i = 0; i < 4; i++) {
                int ks = i * 16;
                #pragma unroll
                for (int p = 0; p < 4; p++) {
                    int rb = (p * 16 + n_off) * 72 + ks + kB;
                    uint32_t bh[4], bl[4];
                    ldsm4(bh, kh_b + 2 * rb);
                    ldsm4(bl, kl_b + 2 * rb);
                    #pragma unroll
                    for (int hf = 0; hf < 2; hf++) {
                        int nt = p * 2 + hf;
                        mma16816(sc[nt], qfh[i], bh + hf * 2);
                        mma16816(sc[nt], qfh[i], bl + hf * 2);
                        mma16816(sc[nt], qfl[i], bh + hf * 2);
                    }
                }
            }

            // ---- causal mask (diagonal chunk) ----
            if (t == qt) {
                int r0 = rw + g;
                #pragma unroll
                for (int nt = 0; nt < 8; nt++) {
                    int c0 = nt * 8 + 2 * tg;
                    if (c0     > r0)     sc[nt][0] = -INFINITY;
                    if (c0 + 1 > r0)     sc[nt][1] = -INFINITY;
                    if (c0     > r0 + 8) sc[nt][2] = -INFINITY;
                    if (c0 + 1 > r0 + 8) sc[nt][3] = -INFINITY;
                }
            }

            // ---- row max + rescale ----
            float mx0 = -INFINITY, mx1 = -INFINITY;
            #pragma unroll
            for (int nt = 0; nt < 8; nt++) {
                mx0 = fmaxf(mx0, fmaxf(sc[nt][0], sc[nt][1]));
                mx1 = fmaxf(mx1, fmaxf(sc[nt][2], sc[nt][3]));
            }
            mx0 = fmaxf(mx0, __shfl_xor_sync(0xffffffffu, mx0, 1));
            mx0 = fmaxf(mx0, __shfl_xor_sync(0xffffffffu, mx0, 2));
            mx1 = fmaxf(mx1, __shfl_xor_sync(0xffffffffu, mx1, 1));
            mx1 = fmaxf(mx1, __shfl_xor_sync(0xffffffffu, mx1, 2));

            float mn0 = fmaxf(m_i[0], mx0);
            float mn1 = fmaxf(m_i[1], mx1);
            float al0 = ex2(m_i[0] - mn0);
            float al1 = ex2(m_i[1] - mn1);
            m_i[0] = mn0;
            m_i[1] = mn1;
            #pragma unroll
            for (int nt = 0; nt < 8; nt++) {
                o[nt][0] *= al0; o[nt][1] *= al0;
                o[nt][2] *= al1; o[nt][3] *= al1;
            }

            // ---- interleaved exp + pack + PV mma per P-fragment ----
            float rs0 = 0.f, rs1 = 0.f;
            #pragma unroll
            for (int kk = 0; kk < 4; kk++) {
                int j0 = 2 * kk;
                float p00 = ex2(sc[j0][0] - mn0),     p01 = ex2(sc[j0][1] - mn0);
                float p02 = ex2(sc[j0][2] - mn1),     p03 = ex2(sc[j0][3] - mn1);
                float p10 = ex2(sc[j0 + 1][0] - mn0), p11 = ex2(sc[j0 + 1][1] - mn0);
                float p12 = ex2(sc[j0 + 1][2] - mn1), p13 = ex2(sc[j0 + 1][3] - mn1);
                rs0 += (p00 + p01) + (p10 + p11);
                rs1 += (p02 + p03) + (p12 + p13);
                uint32_t ph[4], pl[4];
                ph[0] = hi2(p00, p01);  pl[0] = lo2(p00, p01);
                ph[1] = hi2(p02, p03);  pl[1] = lo2(p02, p03);
                ph[2] = hi2(p10, p11);  pl[2] = lo2(p10, p11);
                ph[3] = hi2(p12, p13);  pl[3] = lo2(p12, p13);
                #pragma unroll
                for (int p = 0; p < 4; p++) {
                    int rb = (p * 16 + n_off) * 72 + kk * 16 + kB;
                    uint32_t bvh[4], bvl[4];
                    ldsm4(bvh, vh_b + 2 * rb);
                    ldsm4(bvl, vl_b + 2 * rb);
                    #pragma unroll
                    for (int hf = 0; hf < 2; hf++) {
                        int nt = p * 2 + hf;
                        mma16816(o[nt], ph, bvh + hf * 2);
                        mma16816(o[nt], ph, bvl + hf * 2);
                        mma16816(o[nt], pl, bvh + hf * 2);
                    }
                }
            }
            rs0 += __shfl_xor_sync(0xffffffffu, rs0, 1);
            rs0 += __shfl_xor_sync(0xffffffffu, rs0, 2);
            rs1 += __shfl_xor_sync(0xffffffffu, rs1, 1);
            rs1 += __shfl_xor_sync(0xffffffffu, rs1, 2);
            l_i[0] = l_i[0] * al0 + rs0;
            l_i[1] = l_i[1] * al1 + rs1;

            __syncthreads();
            if (t + 2 <= qt) issue_kv(t + 2, s);
            CP_COMMIT();
        }

        // ---- epilogue ----
        float inv0 = 1.f / l_i[0];
        float inv1 = 1.f / l_i[1];
        int row0 = q0 + rw + g;
        #pragma unroll
        for (int nt = 0; nt < 8; nt++) {
            *(float2*)&out[((size_t)b * TT + row0) * HH + nt * 8 + 2 * tg] =
                make_float2(o[nt][0] * inv0, o[nt][1] * inv0);
            *(float2*)&out[((size_t)b * TT + row0 + 8) * HH + nt * 8 + 2 * tg] =
                make_float2(o[nt][2] * inv1, o[nt][3] * inv1);
        }
    }

    if (tid == 0) {
        if (atomicAdd(&g_done, 1) == ATTN_CTAS - 1) {
            g_ctr  = 0;
            g_done = 0;
        }
    }
}

extern "C" void kernel_launch(void* const* d_in, const int* in_sizes, int n_in,
                              void* d_out, int out_size)
{
    const float* x  = (const float*)d_in[0];
    const float* Wq = (const float*)d_in[1];
    const float* Wk = (const float*)d_in[2];
    const float* Wv = (const float*)d_in[3];
    float* out = (float*)d_out;

    cudaFuncSetAttribute(proj_mma_kernel,
                         cudaFuncAttributeMaxDynamicSharedMemorySize, PROJ_SMEM);
    cudaFuncSetAttribute(attn_mma_kernel,
                         cudaFuncAttributeMaxDynamicSharedMemorySize, ATTN_SMEM);

    wprep_kernel<<<192, 256>>>(Wq, Wk, Wv);
    xprep_kernel<<<2048, 256>>>(x);
    proj_mma_kernel<<<dim3(128, 2), 256, PROJ_SMEM>>>();
    attn_mma_kernel<<<ATTN_CTAS, 128, ATTN_SMEM>>>(out);
}

// round 11
// speedup vs baseline: 1.1737x; 1.1737x over previous
#include <cuda_runtime.h>
#include <cuda_bf16.h>
#include <math.h>
#include <cstdint>

#define BB 8
#define TT 2048
#define CC 1024
#define HH 64

// bf16 hi/lo tensors
__device__ __nv_bfloat16 g_xh[BB*TT*CC], g_xl[BB*TT*CC];   // x  [m][c]
__device__ __nv_bfloat16 g_qh[BB*TT*HH], g_ql[BB*TT*HH];   // q  [b][t][h] (x 0.125*log2e)
__device__ __nv_bfloat16 g_kh[BB*TT*HH], g_kl[BB*TT*HH];   // k  [b][t][h]
__device__ __nv_bfloat16 g_vth[BB*HH*TT], g_vtl[BB*HH*TT]; // v^T [b][h][t]
__device__ __nv_bfloat16 g_wt_hi[192*CC];                  // W^T [n][k], n = mat*64+h
__device__ __nv_bfloat16 g_wt_lo[192*CC];
__device__ int g_ctr  = 0;
__device__ int g_done = 0;

// split-tile partials: tiles with qt in [16,31], 2 segments each
__device__ float g_po[8*16*2*64*64];   // unnormalized O
__device__ float g_pm[8*16*2*64];      // row max (log2 domain)
__device__ float g_pl[8*16*2*64];      // row sum
__device__ int   g_cnt[8*16];          // arrival counters (zero-init)

// ---- mma.sync m16n8k16 bf16 (sm_80 baseline) ----
__device__ __forceinline__ void mma16816(float* c, const uint32_t* a, const uint32_t* b) {
    asm volatile(
        "mma.sync.aligned.m16n8k16.row.col.f32.bf16.bf16.f32 "
        "{%0,%1,%2,%3}, {%4,%5,%6,%7}, {%8,%9}, {%0,%1,%2,%3};"
        : "+f"(c[0]), "+f"(c[1]), "+f"(c[2]), "+f"(c[3])
        : "r"(a[0]), "r"(a[1]), "r"(a[2]), "r"(a[3]), "r"(b[0]), "r"(b[1]));
}
__device__ __forceinline__ void ldsm4(uint32_t* r, uint32_t addr) {
    asm volatile("ldmatrix.sync.aligned.m8n8.x4.shared.b16 {%0,%1,%2,%3}, [%4];"
        : "=r"(r[0]), "=r"(r[1]), "=r"(r[2]), "=r"(r[3]) : "r"(addr) : "memory");
}
#define CP16(dst, src) asm volatile("cp.async.cg.shared.global [%0], [%1], 16;" :: "r"(dst), "l"(src) : "memory")
#define CP_COMMIT()    asm volatile("cp.async.commit_group;" ::: "memory")
#define CP_WAIT1()     asm volatile("cp.async.wait_group 1;" ::: "memory")

__device__ __forceinline__ uint32_t smem_u32(const void* p) {
    uint32_t a;
    asm("{ .reg .u64 t; cvta.to.shared.u64 t, %1; cvt.u32.u64 %0, t; }" : "=r"(a) : "l"(p));
    return a;
}
__device__ __forceinline__ float ex2(float x) {
    float y; asm("ex2.approx.f32 %0, %1;" : "=f"(y) : "f"(x)); return y;
}
__device__ __forceinline__ uint32_t hi2(float a, float b) {
    return ((uint32_t)__bfloat16_as_ushort(__float2bfloat16(b)) << 16) |
           (uint32_t)__bfloat16_as_ushort(__float2bfloat16(a));
}
__device__ __forceinline__ uint32_t lo2(float a, float b) {
    float ra = a - __bfloat162float(__float2bfloat16(a));
    float rb = b - __bfloat162float(__float2bfloat16(b));
    return hi2(ra, rb);
}

// ---------------------------------------------------------------------------
// Prep kernels
// ---------------------------------------------------------------------------
__global__ __launch_bounds__(256) void wprep_kernel(
    const float* __restrict__ Wq, const float* __restrict__ Wk,
    const float* __restrict__ Wv)
{
    int n = blockIdx.x;
    const float* W = (n < 64) ? Wq : (n < 128) ? Wk : Wv;
    int h = n & 63;
    for (int k = threadIdx.x; k < CC; k += 256) {
        float v = W[(size_t)k * HH + h];
        __nv_bfloat16 hi = __float2bfloat16(v);
        g_wt_hi[(size_t)n * CC + k] = hi;
        g_wt_lo[(size_t)n * CC + k] = __float2bfloat16(v - __bfloat162float(hi));
    }
}

__global__ __launch_bounds__(256) void xprep_kernel(const float* __restrict__ x)
{
    const int stride = gridDim.x * blockDim.x;
    for (int i = blockIdx.x * blockDim.x + threadIdx.x; i < BB*TT*CC/4; i += stride) {
        float4 v = *(const float4*)&x[(size_t)i * 4];
        uint2 hv, lv;
        hv.x = hi2(v.x, v.y);  hv.y = hi2(v.z, v.w);
        lv.x = lo2(v.x, v.y);  lv.y = lo2(v.z, v.w);
        *(uint2*)&g_xh[(size_t)i * 4] = hv;
        *(uint2*)&g_xl[(size_t)i * 4] = lv;
    }
}

// ---------------------------------------------------------------------------
// Projection GEMM (R9 layout): 128 CTAs x 256 thr, N=192, K chunks of 32.
// smem per stage: Ah@0(5120) Al@5120 Bh@10240(7680) Bl@17920; PSS 25600 bf16
// ---------------------------------------------------------------------------
#define PROJ_SMEM 102400
#define PSS 25600

__global__ __launch_bounds__(256, 1) void proj_mma_kernel()
{
    extern __shared__ __nv_bfloat16 sb[];
    const uint32_t sbase = smem_u32(sb);

    const int tid  = threadIdx.x;
    const int wid  = tid >> 5;
    const int lane = tid & 31;
    const int g    = lane >> 2;
    const int tg   = lane & 3;
    const int m0   = blockIdx.x * 128;
    const int m0w  = (wid >> 1) * 32;
    const int n0w  = (wid & 1) * 96;

    const int m_off = (lane & 7) + ((lane >> 3) & 1) * 8;
    const int kA    = (lane >> 4) * 8;
    const int n_off = (lane & 7) + ((lane >> 4) & 1) * 8;
    const int kB    = ((lane >> 3) & 1) * 8;

    auto issue_chunk = [&](int kc, int s) {
        const int k0 = kc * 32;
        const uint32_t st = sbase + 2 * (s * PSS);
        #pragma unroll
        for (int t = 0; t < 4; t++) {
            int e = tid + t * 256;
            int arr = e >> 9;
            int ee  = e & 511;
            int row = ee >> 2, q = ee & 3;
            const __nv_bfloat16* src =
                (arr ? g_xl : g_xh) + (size_t)(m0 + row) * CC + k0 + q * 8;
            CP16(st + 2 * (arr * 5120 + row * 40 + q * 8), src);
        }
        #pragma unroll
        for (int t = 0; t < 6; t++) {
            int e = tid + t * 256;
            int arr = (e >= 768);
            int ee  = arr ? e - 768 : e;
            int row = ee >> 2, q = ee & 3;
            const __nv_bfloat16* src =
                (arr ? g_wt_lo : g_wt_hi) + (size_t)row * CC + k0 + q * 8;
            CP16(st + 2 * (10240 + arr * 7680 + row * 40 + q * 8), src);
        }
    };

    float acc[2][12][4];
    #pragma unroll
    for (int mt = 0; mt < 2; mt++)
        #pragma unroll
        for (int nt = 0; nt < 12; nt++)
            #pragma unroll
            for (int i = 0; i < 4; i++) acc[mt][nt][i] = 0.f;

    issue_chunk(0, 0); CP_COMMIT();
    issue_chunk(1, 1); CP_COMMIT();

    for (int kc = 0; kc < 32; kc++) {
        const int s = kc & 1;
        CP_WAIT1();
        __syncthreads();

        const uint32_t ah_b = sbase + 2 * (s * PSS);
        const uint32_t al_b = ah_b + 2 * 5120;
        const uint32_t bh_b = ah_b + 2 * 10240;
        const uint32_t bl_b = ah_b + 2 * 17920;

        #pragma unroll
        for (int ks = 0; ks < 32; ks += 16) {
            uint32_t ah[2][4], al[2][4];
            #pragma unroll
            for (int mt = 0; mt < 2; mt++) {
                int ro = (m0w + mt * 16 + m_off) * 40 + ks + kA;
                ldsm4(ah[mt], ah_b + 2 * ro);
                ldsm4(al[mt], al_b + 2 * ro);
            }
            #pragma unroll
            for (int p = 0; p < 6; p++) {
                int ro = (n0w + p * 16 + n_off) * 40 + ks + kB;
                uint32_t bh[4], bl[4];
                ldsm4(bh, bh_b + 2 * ro);
                ldsm4(bl, bl_b + 2 * ro);
                #pragma unroll
                for (int hf = 0; hf < 2; hf++) {
                    int nt = p * 2 + hf;
                    #pragma unroll
                    for (int mt = 0; mt < 2; mt++) {
                        mma16816(acc[mt][nt], ah[mt], bh + hf * 2);
                        mma16816(acc[mt][nt], ah[mt], bl + hf * 2);
                        mma16816(acc[mt][nt], al[mt], bh + hf * 2);
                    }
                }
            }
        }
        __syncthreads();
        if (kc + 2 < 32) issue_chunk(kc + 2, s);
        CP_COMMIT();
    }

    // ---- epilogue ----
    const int b  = m0 >> 11;
    const int t0 = m0 & 2047;
    const float QSC = 0.125f * 1.44269504088896f;   // fold log2e for exp2 softmax
    __nv_bfloat16* sTh = sb;               // [64][136]
    __nv_bfloat16* sTl = sb + 64 * 136;

    #pragma unroll
    for (int nt = 0; nt < 12; nt++) {
        int nbase = n0w + nt * 8;
        #pragma unroll
        for (int mt = 0; mt < 2; mt++) {
            int row = m0w + mt * 16 + g;
            float c0 = acc[mt][nt][0], c1 = acc[mt][nt][1];
            float c2 = acc[mt][nt][2], c3 = acc[mt][nt][3];
            if (nbase < 64) {
                c0 *= QSC; c1 *= QSC; c2 *= QSC; c3 *= QSC;
                size_t base0 = (size_t)(m0 + row) * HH + nbase + 2 * tg;
                size_t base1 = base0 + 8 * HH;
                *(uint32_t*)&g_qh[base0] = hi2(c0, c1);
                *(uint32_t*)&g_ql[base0] = lo2(c0, c1);
                *(uint32_t*)&g_qh[base1] = hi2(c2, c3);
                *(uint32_t*)&g_ql[base1] = lo2(c2, c3);
            } else if (nbase < 128) {
                size_t base0 = (size_t)(m0 + row) * HH + (nbase - 64) + 2 * tg;
                size_t base1 = base0 + 8 * HH;
                *(uint32_t*)&g_kh[base0] = hi2(c0, c1);
                *(uint32_t*)&g_kl[base0] = lo2(c0, c1);
                *(uint32_t*)&g_kh[base1] = hi2(c2, c3);
                *(uint32_t*)&g_kl[base1] = lo2(c2, c3);
            } else {
                int h = nbase - 128 + 2 * tg;
                __nv_bfloat16 h0 = __float2bfloat16(c0), h1 = __float2bfloat16(c1);
                __nv_bfloat16 h2 = __float2bfloat16(c2), h3 = __float2bfloat16(c3);
                sTh[h * 136 + row]           = h0;
                sTh[(h + 1) * 136 + row]     = h1;
                sTh[h * 136 + row + 8]       = h2;
                sTh[(h + 1) * 136 + row + 8] = h3;
                sTl[h * 136 + row]           = __float2bfloat16(c0 - __bfloat162float(h0));
                sTl[(h + 1) * 136 + row]     = __float2bfloat16(c1 - __bfloat162float(h1));
                sTl[h * 136 + row + 8]       = __float2bfloat16(c2 - __bfloat162float(h2));
                sTl[(h + 1) * 136 + row + 8] = __float2bfloat16(c3 - __bfloat162float(h3));
            }
        }
    }
    __syncthreads();
    #pragma unroll
    for (int t = 0; t < 8; t++) {
        int e   = tid + t * 256;
        int arr = e >> 10;
        int ee  = e & 1023;
        int h   = ee >> 4;
        int q   = ee & 15;
        uint4 v4 = *(const uint4*)&(arr ? sTl : sTh)[h * 136 + q * 8];
        __nv_bfloat16* dst = arr ? g_vtl : g_vth;
        *(uint4*)&dst[(size_t)(b * 64 + h) * 2048 + t0 + q * 8] = v4;
    }
}

// ---------------------------------------------------------------------------
// Attention: KV-split jobs.  Tiles qt>=16 split into 2 segments (<=16 chunks);
// partials combined by the second-finishing CTA.  384 jobs, 304 CTAs.
// smem (bf16, stride 72): Qh@0 Ql@4608; stage s @9216+s*18432:
//   Kh+0 Kl+4608 Vh+9216 Vl+13824.  total 92160 B
// ---------------------------------------------------------------------------
#define ATTN_CTAS 304
#define ATTN_JOBS 384
#define ATTN_SMEM 92160

__global__ __launch_bounds__(128, 1) void attn_mma_kernel(float* __restrict__ out)
{
    extern __shared__ __nv_bfloat16 sab[];
    const uint32_t sbase = smem_u32(sab);
    __shared__ int sJob;
    __shared__ int sLast;

    const int tid  = threadIdx.x;
    const int wid  = tid >> 5;
    const int lane = tid & 31;
    const int g    = lane >> 2;
    const int tg   = lane & 3;
    const int rw   = wid * 16;

    const int m_off = (lane & 7) + ((lane >> 3) & 1) * 8;
    const int kA    = (lane >> 4) * 8;
    const int n_off = (lane & 7) + ((lane >> 4) & 1) * 8;
    const int kB    = ((lane >> 3) & 1) * 8;

    for (;;) {
        if (tid == 0) sJob = atomicAdd(&g_ctr, 1);
        __syncthreads();
        const int job = sJob;
        if (job >= ATTN_JOBS) break;

        // ---- decode job: heavy segments first ----
        int qt, b, segid, seg0, segn, split;
        if (job < 256) {               // qt 31..16, 8 batches, 2 segments
            qt    = 31 - (job >> 4);
            b     = (job >> 1) & 7;
            segid = job & 1;
            split = 1;
            int total = qt + 1;
            int h = (total + 1) >> 1;
            if (segid == 0) { seg0 = 0; segn = h; }
            else            { seg0 = h; segn = total - h; }
        } else {                       // qt 15..0, unsplit
            int j2 = job - 256;
            qt = 15 - (j2 >> 3);
            b  = j2 & 7;
            segid = 0; split = 0; seg0 = 0; segn = qt + 1;
        }
        const int q0 = qt * 64;

        auto issue_kv = [&](int t, int s) {
            const int kv0 = t * 64;
            const uint32_t st = sbase + 2 * (9216 + s * 18432);
            #pragma unroll
            for (int tt = 0; tt < 16; tt++) {
                int e = tid + tt * 128;
                int arr = e >> 9;            // 0:Kh 1:Kl 2:Vh 3:Vl
                int ee  = e & 511;
                int row = ee >> 3, q = ee & 7;
                const __nv_bfloat16* src;
                if (arr == 0)      src = g_kh  + ((size_t)b * TT + kv0 + row) * HH + q * 8;
                else if (arr == 1) src = g_kl  + ((size_t)b * TT + kv0 + row) * HH + q * 8;
                else if (arr == 2) src = g_vth + ((size_t)(b * 64 + row)) * 2048 + kv0 + q * 8;
                else               src = g_vtl + ((size_t)(b * 64 + row)) * 2048 + kv0 + q * 8;
                CP16(st + 2 * (arr * 4608 + row * 72 + q * 8), src);
            }
        };

        // group 0: Q + KV chunk seg0;  group 1: KV chunk seg0+1 (if any)
        #pragma unroll
        for (int tt = 0; tt < 8; tt++) {
            int e = tid + tt * 128;
            int arr = e >> 9;
            int ee  = e & 511;
            int row = ee >> 3, q = ee & 7;
            const __nv_bfloat16* src =
                (arr ? g_ql : g_qh) + ((size_t)b * TT + q0 + row) * HH + q * 8;
            CP16(sbase + 2 * (arr * 4608 + row * 72 + q * 8), src);
        }
        issue_kv(seg0, 0); CP_COMMIT();
        if (segn >= 2) issue_kv(seg0 + 1, 1);
        CP_COMMIT();

        // hoist Q fragments (arrive with group 0)
        CP_WAIT1();
        __syncthreads();
        uint32_t qfh[4][4], qfl[4][4];
        #pragma unroll
        for (int i = 0; i < 4; i++) {
            int ro = (rw + m_off) * 72 + i * 16 + kA;
            ldsm4(qfh[i], sbase + 2 * ro);
            ldsm4(qfl[i], sbase + 2 * (4608 + ro));
        }

        float m_i[2] = {-INFINITY, -INFINITY};
        float l_i[2] = {0.f, 0.f};
        float o[8][4];
        #pragma unroll
        for (int nt = 0; nt < 8; nt++)
            #pragma unroll
            for (int i = 0; i < 4; i++) o[nt][i] = 0.f;

        for (int tt = 0; tt < segn; tt++) {
            const int t = seg0 + tt;
            const int s = tt & 1;
            CP_WAIT1();
            __syncthreads();

            const uint32_t kh_b = sbase + 2 * (9216 + s * 18432);
            const uint32_t kl_b = kh_b + 2 * 4608;
            const uint32_t vh_b = kh_b + 2 * 9216;
            const uint32_t vl_b = kh_b + 2 * 13824;

            float sc[8][4];
            #pragma unroll
            for (int nt = 0; nt < 8; nt++)
                #pragma unroll
                for (int i = 0; i < 4; i++) sc[nt][i] = 0.f;

            #pragma unroll
            for (int i = 0; i < 4; i++) {
                int ks = i * 16;
                #pragma unroll
                for (int p = 0; p < 4; p++) {
                    int rb = (p * 16 + n_off) * 72 + ks + kB;
                    uint32_t bh[4], bl[4];
                    ldsm4(bh, kh_b + 2 * rb);
                    ldsm4(bl, kl_b + 2 * rb);
                    #pragma unroll
                    for (int hf = 0; hf < 2; hf++) {
                        int nt = p * 2 + hf;
                        mma16816(sc[nt], qfh[i], bh + hf * 2);
                        mma16816(sc[nt], qfh[i], bl + hf * 2);
                        mma16816(sc[nt], qfl[i], bh + hf * 2);
                    }
                }
            }

            if (t == qt) {   // diagonal chunk: causal mask
                int r0 = rw + g;
                #pragma unroll
                for (int nt = 0; nt < 8; nt++) {
                    int c0 = nt * 8 + 2 * tg;
                    if (c0     > r0)     sc[nt][0] = -INFINITY;
                    if (c0 + 1 > r0)     sc[nt][1] = -INFINITY;
                    if (c0     > r0 + 8) sc[nt][2] = -INFINITY;
                    if (c0 + 1 > r0 + 8) sc[nt][3] = -INFINITY;
                }
            }

            float mx0 = -INFINITY, mx1 = -INFINITY;
            #pragma unroll
            for (int nt = 0; nt < 8; nt++) {
                mx0 = fmaxf(mx0, fmaxf(sc[nt][0], sc[nt][1]));
                mx1 = fmaxf(mx1, fmaxf(sc[nt][2], sc[nt][3]));
            }
            mx0 = fmaxf(mx0, __shfl_xor_sync(0xffffffffu, mx0, 1));
            mx0 = fmaxf(mx0, __shfl_xor_sync(0xffffffffu, mx0, 2));
            mx1 = fmaxf(mx1, __shfl_xor_sync(0xffffffffu, mx1, 1));
            mx1 = fmaxf(mx1, __shfl_xor_sync(0xffffffffu, mx1, 2));

            float mn0 = fmaxf(m_i[0], mx0);
            float mn1 = fmaxf(m_i[1], mx1);
            float al0 = ex2(m_i[0] - mn0);
            float al1 = ex2(m_i[1] - mn1);
            m_i[0] = mn0;
            m_i[1] = mn1;
            #pragma unroll
            for (int nt = 0; nt < 8; nt++) {
                o[nt][0] *= al0; o[nt][1] *= al0;
                o[nt][2] *= al1; o[nt][3] *= al1;
            }

            float rs0 = 0.f, rs1 = 0.f;
            #pragma unroll
            for (int kk = 0; kk < 4; kk++) {
                int j0 = 2 * kk;
                float p00 = ex2(sc[j0][0] - mn0),     p01 = ex2(sc[j0][1] - mn0);
                float p02 = ex2(sc[j0][2] - mn1),     p03 = ex2(sc[j0][3] - mn1);
                float p10 = ex2(sc[j0 + 1][0] - mn0), p11 = ex2(sc[j0 + 1][1] - mn0);
                float p12 = ex2(sc[j0 + 1][2] - mn1), p13 = ex2(sc[j0 + 1][3] - mn1);
                rs0 += (p00 + p01) + (p10 + p11);
                rs1 += (p02 + p03) + (p12 + p13);
                uint32_t ph[4], pl[4];
                ph[0] = hi2(p00, p01);  pl[0] = lo2(p00, p01);
                ph[1] = hi2(p02, p03);  pl[1] = lo2(p02, p03);
                ph[2] = hi2(p10, p11);  pl[2] = lo2(p10, p11);
                ph[3] = hi2(p12, p13);  pl[3] = lo2(p12, p13);
                #pragma unroll
                for (int p = 0; p < 4; p++) {
                    int rb = (p * 16 + n_off) * 72 + kk * 16 + kB;
                    uint32_t bvh[4], bvl[4];
                    ldsm4(bvh, vh_b + 2 * rb);
                    ldsm4(bvl, vl_b + 2 * rb);
                    #pragma unroll
                    for (int hf = 0; hf < 2; hf++) {
                        int nt = p * 2 + hf;
                        mma16816(o[nt], ph, bvh + hf * 2);
                        mma16816(o[nt], ph, bvl + hf * 2);
                        mma16816(o[nt], pl, bvh + hf * 2);
                    }
                }
            }
            rs0 += __shfl_xor_sync(0xffffffffu, rs0, 1);
            rs0 += __shfl_xor_sync(0xffffffffu, rs0, 2);
            rs1 += __shfl_xor_sync(0xffffffffu, rs1, 1);
            rs1 += __shfl_xor_sync(0xffffffffu, rs1, 2);
            l_i[0] = l_i[0] * al0 + rs0;
            l_i[1] = l_i[1] * al1 + rs1;

            __syncthreads();
            if (tt + 2 < segn) issue_kv(seg0 + tt + 2, s);
            CP_COMMIT();
        }

        // ---- epilogue ----
        if (!split) {
            float inv0 = 1.f / l_i[0];
            float inv1 = 1.f / l_i[1];
            int row0 = q0 + rw + g;
            #pragma unroll
            for (int nt = 0; nt < 8; nt++) {
                *(float2*)&out[((size_t)b * TT + row0) * HH + nt * 8 + 2 * tg] =
                    make_float2(o[nt][0] * inv0, o[nt][1] * inv0);
                *(float2*)&out[((size_t)b * TT + row0 + 8) * HH + nt * 8 + 2 * tg] =
                    make_float2(o[nt][2] * inv1, o[nt][3] * inv1);
            }
        } else {
            const int qi   = qt - 16;
            const int tile = b * 16 + qi;
            float* po = g_po + (size_t)(tile * 2 + segid) * 4096;
            float* pm = g_pm + (size_t)(tile * 2 + segid) * 64;
            float* pl = g_pl + (size_t)(tile * 2 + segid) * 64;
            int r0 = rw + g;
            #pragma unroll
            for (int nt = 0; nt < 8; nt++) {
                *(float2*)&po[r0 * 64 + nt * 8 + 2 * tg]       = make_float2(o[nt][0], o[nt][1]);
                *(float2*)&po[(r0 + 8) * 64 + nt * 8 + 2 * tg] = make_float2(o[nt][2], o[nt][3]);
            }
            if (tg == 0) {
                pm[r0] = m_i[0];  pl[r0] = l_i[0];
                pm[r0 + 8] = m_i[1];  pl[r0 + 8] = l_i[1];
            }
            __threadfence();
            __syncthreads();
            if (tid == 0) sLast = atomicAdd(&g_cnt[tile], 1);
            __syncthreads();
            if (sLast == 1) {
                __threadfence();
                const float* po0 = g_po + (size_t)(tile * 2 + 0) * 4096;
                const float* po1 = g_po + (size_t)(tile * 2 + 1) * 4096;
                const float* pm0 = g_pm + (size_t)(tile * 2 + 0) * 64;
                const float* pm1 = g_pm + (size_t)(tile * 2 + 1) * 64;
                const float* pl0 = g_pl + (size_t)(tile * 2 + 0) * 64;
                const float* pl1 = g_pl + (size_t)(tile * 2 + 1) * 64;
                int r  = tid >> 1;           // 0..63
                int c0 = (tid & 1) * 32;
                float m0 = pm0[r], m1 = pm1[r];
                float mm = fmaxf(m0, m1);
                float a0 = ex2(m0 - mm), a1 = ex2(m1 - mm);
                float inv = 1.f / (pl0[r] * a0 + pl1[r] * a1);
                float* dst = &out[((size_t)b * TT + q0 + r) * HH + c0];
                #pragma unroll 8
                for (int c = 0; c < 32; c++)
                    dst[c] = (po0[r * 64 + c0 + c] * a0 + po1[r * 64 + c0 + c] * a1) * inv;
                if (tid == 0) g_cnt[tile] = 0;    // reset for next graph replay
            }
        }
    }

    if (tid == 0) {
        if (atomicAdd(&g_done, 1) == ATTN_CTAS - 1) {
            g_ctr  = 0;
            g_done = 0;
        }
    }
}

extern "C" void kernel_launch(void* const* d_in, const int* in_sizes, int n_in,
                              void* d_out, int out_size)
{
    const float* x  = (const float*)d_in[0];
    const float* Wq = (const float*)d_in[1];
    const float* Wk = (const float*)d_in[2];
    const float* Wv = (const float*)d_in[3];
    float* out = (float*)d_out;

    cudaFuncSetAttribute(proj_mma_kernel,
                         cudaFuncAttributeMaxDynamicSharedMemorySize, PROJ_SMEM);
    cudaFuncSetAttribute(attn_mma_kernel,
                         cudaFuncAttributeMaxDynamicSharedMemorySize, ATTN_SMEM);

    wprep_kernel<<<192, 256>>>(Wq, Wk, Wv);
    xprep_kernel<<<2048, 256>>>(x);
    proj_mma_kernel<<<BB * TT / 128, 256, PROJ_SMEM>>>();
    attn_mma_kernel<<<ATTN_CTAS, 128, ATTN_SMEM>>>(out);
}